// round 2
// baseline (speedup 1.0000x reference)
#include <cuda_runtime.h>
#include <cstdint>

// ---------------------------------------------------------------------------
// Problem constants (fixed shapes from reference)
// ---------------------------------------------------------------------------
#define NB_T   4096          // B*T tokens
#define HDIM   4096          // H
#define SDIM   1024          // S sampled dims
#define FDIM   9984          // F ffn dims
#define GORD   6             // Taylor orders
#define KTAY   (SDIM * GORD) // 6144

// ---------------------------------------------------------------------------
// Scratch (static device globals; allocation-free per harness rules)
// ---------------------------------------------------------------------------
__device__ float g_AU [NB_T * SDIM];   // approx_up        [4096,1024]
__device__ float g_GP [NB_T * SDIM];   // gate_pre         [4096,1024]
__device__ float g_TMP[NB_T * KTAY];   // taylor operand   [4096,6144]
__device__ float g_BG [(size_t)NB_T * FDIM]; // ffn gate / fused P [4096,9984]
__device__ float g_BU [(size_t)NB_T * FDIM]; // ffn up             [4096,9984]

// ---------------------------------------------------------------------------
// Generic fp32 GEMM:  C[N,M] (+)= A[N,K] @ B[M,K]^T
// A row-major [N,K], B row-major [M,K], C row-major [N,M].
// Requires N%128==0, M%128==0, K%16==0 (true for all call sites).
// BLOCK 128x128, KT=16, 256 threads, 8x8 per thread (split 4+4 microtile
// so shared loads are LDS.128 conflict-free).
// ---------------------------------------------------------------------------
#define TILE 128
#define KT   16

template <int BETA>
__global__ __launch_bounds__(256, 2)
void gemm_tn(const float* __restrict__ A, const float* __restrict__ B,
             float* __restrict__ C, int N, int M, int K)
{
    __shared__ float As[KT][TILE];
    __shared__ float Bs[KT][TILE];

    const int bx = blockIdx.x;           // M tile
    const int by = blockIdx.y;           // N tile
    const int t  = threadIdx.x;
    const int tx = t & 15;               // 16 col groups
    const int ty = t >> 4;               // 16 row groups

    const float* Ab = A + (size_t)by * TILE * K;
    const float* Bb = B + (size_t)bx * TILE * K;

    float acc[8][8];
#pragma unroll
    for (int i = 0; i < 8; i++)
#pragma unroll
        for (int j = 0; j < 8; j++) acc[i][j] = 0.f;

    for (int k0 = 0; k0 < K; k0 += KT) {
        // cooperative tile load: 512 float4 per operand, 2 per thread
#pragma unroll
        for (int j = 0; j < 2; j++) {
            int idx = t + j * 256;
            int row = idx >> 2;          // 0..127
            int kg  = idx & 3;           // 0..3 (groups of 4 k)
            float4 va = *reinterpret_cast<const float4*>(Ab + (size_t)row * K + k0 + kg * 4);
            As[kg * 4 + 0][row] = va.x;
            As[kg * 4 + 1][row] = va.y;
            As[kg * 4 + 2][row] = va.z;
            As[kg * 4 + 3][row] = va.w;
            float4 vb = *reinterpret_cast<const float4*>(Bb + (size_t)row * K + k0 + kg * 4);
            Bs[kg * 4 + 0][row] = vb.x;
            Bs[kg * 4 + 1][row] = vb.y;
            Bs[kg * 4 + 2][row] = vb.z;
            Bs[kg * 4 + 3][row] = vb.w;
        }
        __syncthreads();

#pragma unroll
        for (int k = 0; k < KT; k++) {
            float a[8], b[8];
            // split microtile: rows {ty*4..+3} and {64+ty*4..+3}; cols likewise.
            // consecutive threads -> consecutive 16B -> conflict-free LDS.128
            *reinterpret_cast<float4*>(a)     = *reinterpret_cast<const float4*>(&As[k][ty * 4]);
            *reinterpret_cast<float4*>(a + 4) = *reinterpret_cast<const float4*>(&As[k][64 + ty * 4]);
            *reinterpret_cast<float4*>(b)     = *reinterpret_cast<const float4*>(&Bs[k][tx * 4]);
            *reinterpret_cast<float4*>(b + 4) = *reinterpret_cast<const float4*>(&Bs[k][64 + tx * 4]);
#pragma unroll
            for (int i = 0; i < 8; i++)
#pragma unroll
                for (int j = 0; j < 8; j++)
                    acc[i][j] = fmaf(a[i], b[j], acc[i][j]);
        }
        __syncthreads();
    }

    // epilogue: 2 row-halves x 2 col-halves
#pragma unroll
    for (int ih = 0; ih < 2; ih++) {
#pragma unroll
        for (int i = 0; i < 4; i++) {
            int row = by * TILE + ih * 64 + ty * 4 + i;
#pragma unroll
            for (int jh = 0; jh < 2; jh++) {
                int col = bx * TILE + jh * 64 + tx * 4;
                float4 v;
                v.x = acc[ih * 4 + i][jh * 4 + 0];
                v.y = acc[ih * 4 + i][jh * 4 + 1];
                v.z = acc[ih * 4 + i][jh * 4 + 2];
                v.w = acc[ih * 4 + i][jh * 4 + 3];
                float4* p = reinterpret_cast<float4*>(C + (size_t)row * M + col);
                if (BETA) {
                    float4 o = *p;
                    v.x += o.x; v.y += o.y; v.z += o.z; v.w += o.w;
                }
                *p = v;
            }
        }
    }
}

// ---------------------------------------------------------------------------
// Taylor coefficient kernel:
// TMP[t, s*6+g] = sign-corrected exp(m*log|delta| - log(m!)) * AU[t,s]
//                 * (|delta|<=2.5 for m>4)
// one thread per (t,s)
// ---------------------------------------------------------------------------
__global__ void taylor_kernel(const float* __restrict__ AU,
                              const float* __restrict__ GP,
                              const float* __restrict__ lp,
                              const float* __restrict__ df,
                              float* __restrict__ TMP)
{
    int idx = blockIdx.x * blockDim.x + threadIdx.x;   // t*1024 + s
    if (idx >= NB_T * SDIM) return;
    int s = idx & (SDIM - 1);

    float au    = AU[idx];
    float delta = GP[idx] - lp[s];
    float neg   = (delta > 0.f) ? 1.f : -1.f;
    float ad    = fabsf(delta);
    float ld    = logf(ad);                 // delta==0 -> -inf -> exp -> 0 (matches jnp)
    float keep  = (ad <= 2.5f) ? 1.f : 0.f;

    float o[GORD];
#pragma unroll
    for (int g = 0; g < GORD; g++) {
        int   m     = g + 1;
        float dterm = expf(ld * (float)m - df[g]);
        if (m & 1) dterm *= neg;
        float v = dterm * au;
        if (m > 4) v *= keep;               // GRAD_ORDER_MIN = 4
        o[g] = v;
    }
    float* p = TMP + (size_t)idx * GORD;    // 24B stride, 8B aligned
    reinterpret_cast<float2*>(p)[0] = make_float2(o[0], o[1]);
    reinterpret_cast<float2*>(p)[1] = make_float2(o[2], o[3]);
    reinterpret_cast<float2*>(p)[2] = make_float2(o[4], o[5]);
}

// ---------------------------------------------------------------------------
// P = silu(G) * U   (vectorized float4, in-place into G)
// ---------------------------------------------------------------------------
__global__ void silu_mul4(float4* __restrict__ G, const float4* __restrict__ U, int n4)
{
    int i = blockIdx.x * blockDim.x + threadIdx.x;
    if (i >= n4) return;
    float4 g = G[i];
    float4 u = U[i];
    g.x = g.x / (1.f + expf(-g.x)) * u.x;
    g.y = g.y / (1.f + expf(-g.y)) * u.y;
    g.z = g.z / (1.f + expf(-g.z)) * u.z;
    g.w = g.w / (1.f + expf(-g.w)) * u.w;
    G[i] = g;
}

// ---------------------------------------------------------------------------
// kernel_launch
// inputs (metadata order): hidden_states, up_w, gate_w, local_point,
//   local_approx_output, fuse_weight, discount_factor,
//   ffn_gate_w, ffn_up_w, ffn_down_w
// ---------------------------------------------------------------------------
extern "C" void kernel_launch(void* const* d_in, const int* in_sizes, int n_in,
                              void* d_out, int out_size)
{
    const float* X    = (const float*)d_in[0];   // [4096, 4096]
    const float* upw  = (const float*)d_in[1];   // [1024, 4096]
    const float* gw   = (const float*)d_in[2];   // [1024, 4096]
    const float* lp   = (const float*)d_in[3];   // [1024]
    const float* lao  = (const float*)d_in[4];   // [4096, 1024]
    const float* fw   = (const float*)d_in[5];   // [4096, 1024, 6] -> [4096, 6144]
    const float* df   = (const float*)d_in[6];   // [6]
    const float* fgw  = (const float*)d_in[7];   // [9984, 4096]
    const float* fuw  = (const float*)d_in[8];   // [9984, 4096]
    const float* fdw  = (const float*)d_in[9];   // [4096, 9984]
    float* out        = (float*)d_out;           // [4096, 4096]

    float *AU, *GP, *TMP, *BG, *BU;
    cudaGetSymbolAddress((void**)&AU,  g_AU);
    cudaGetSymbolAddress((void**)&GP,  g_GP);
    cudaGetSymbolAddress((void**)&TMP, g_TMP);
    cudaGetSymbolAddress((void**)&BG,  g_BG);
    cudaGetSymbolAddress((void**)&BU,  g_BU);

    // 1,2: sampled-dim projections
    gemm_tn<0><<<dim3(SDIM / TILE, NB_T / TILE), 256>>>(X, upw, AU, NB_T, SDIM, HDIM);
    gemm_tn<0><<<dim3(SDIM / TILE, NB_T / TILE), 256>>>(X, gw,  GP, NB_T, SDIM, HDIM);

    // 3: Taylor coefficients
    taylor_kernel<<<(NB_T * SDIM) / 256, 256>>>(AU, GP, lp, df, TMP);

    // 4: zeroth-order term (writes full output)
    gemm_tn<0><<<dim3(HDIM / TILE, NB_T / TILE), 256>>>(AU, lao, out, NB_T, HDIM, SDIM);

    // 5: all 6 Taylor orders as one GEMM over K = S*G = 6144 (accumulate)
    gemm_tn<1><<<dim3(HDIM / TILE, NB_T / TILE), 256>>>(TMP, fw, out, NB_T, HDIM, KTAY);

    // 6,7: FFN gate / up
    gemm_tn<0><<<dim3(FDIM / TILE, NB_T / TILE), 256>>>(X, fgw, BG, NB_T, FDIM, HDIM);
    gemm_tn<0><<<dim3(FDIM / TILE, NB_T / TILE), 256>>>(X, fuw, BU, NB_T, FDIM, HDIM);

    // 8: P = silu(G) * U
    {
        int n4 = (NB_T * FDIM) / 4;   // 10,223,616
        silu_mul4<<<(n4 + 255) / 256, 256>>>((float4*)BG, (const float4*)BU, n4);
    }

    // 9: FFN down (accumulate)
    gemm_tn<1><<<dim3(HDIM / TILE, NB_T / TILE), 256>>>(BG, fdw, out, NB_T, HDIM, FDIM);
}

// round 6
// speedup vs baseline: 2.3347x; 2.3347x over previous
#include <cuda_runtime.h>
#include <cuda_bf16.h>
#include <cstdint>

// ---------------------------------------------------------------------------
// Shapes (fixed)
// ---------------------------------------------------------------------------
#define NTOK 4096            // B*T
#define HDIM 4096
#define SDIM 1024
#define FDIM 9984
#define KTAY 6144            // S*G

// ---------------------------------------------------------------------------
// Scratch (__device__ globals; allocation-free)
// ---------------------------------------------------------------------------
__device__ __nv_bfloat16 g_Xhi [NTOK * HDIM], g_Xlo [NTOK * HDIM];
__device__ __nv_bfloat16 g_upwh[SDIM * HDIM], g_upwl[SDIM * HDIM];
__device__ __nv_bfloat16 g_gwh [SDIM * HDIM], g_gwl [SDIM * HDIM];
__device__ __nv_bfloat16 g_laoh[HDIM * SDIM], g_laol[HDIM * SDIM];
__device__ __nv_bfloat16 g_fwh [HDIM * KTAY], g_fwl [HDIM * KTAY];
__device__ __nv_bfloat16 g_fgwh[(size_t)FDIM * HDIM], g_fgwl[(size_t)FDIM * HDIM];
__device__ __nv_bfloat16 g_fuwh[(size_t)FDIM * HDIM], g_fuwl[(size_t)FDIM * HDIM];
__device__ __nv_bfloat16 g_fdwh[(size_t)HDIM * FDIM], g_fdwl[(size_t)HDIM * FDIM];
__device__ float         g_AU  [NTOK * SDIM], g_GP  [NTOK * SDIM];
__device__ __nv_bfloat16 g_AUh [NTOK * SDIM], g_AUl [NTOK * SDIM];
__device__ __nv_bfloat16 g_TMPh[NTOK * KTAY], g_TMPl[NTOK * KTAY];
__device__ float         g_BG  [(size_t)NTOK * FDIM], g_BU[(size_t)NTOK * FDIM];
__device__ __nv_bfloat16 g_Ph  [(size_t)NTOK * FDIM], g_Pl[(size_t)NTOK * FDIM];

// ---------------------------------------------------------------------------
// Baseline-PTX tensor-core helpers (no 'a'-gated instructions)
// ---------------------------------------------------------------------------
__device__ __forceinline__ uint32_t smem_u32(const void* p) {
    uint32_t a;
    asm("{ .reg .u64 t; cvta.to.shared.u64 t, %1; cvt.u32.u64 %0, t; }" : "=r"(a) : "l"(p));
    return a;
}
__device__ __forceinline__ void cpasync16(uint32_t dst, const void* src) {
    asm volatile("cp.async.cg.shared.global [%0], [%1], 16;" :: "r"(dst), "l"(src) : "memory");
}
__device__ __forceinline__ void cp_commit() {
    asm volatile("cp.async.commit_group;" ::: "memory");
}
template <int N>
__device__ __forceinline__ void cp_wait() {
    asm volatile("cp.async.wait_group %0;" :: "n"(N) : "memory");
}
__device__ __forceinline__ void ldm4(uint32_t* r, uint32_t a) {
    asm volatile("ldmatrix.sync.aligned.m8n8.x4.shared.b16 {%0,%1,%2,%3}, [%4];"
                 : "=r"(r[0]), "=r"(r[1]), "=r"(r[2]), "=r"(r[3]) : "r"(a));
}
__device__ __forceinline__ void mma16816(float* d, const uint32_t* a, uint32_t b0, uint32_t b1) {
    asm volatile("mma.sync.aligned.m16n8k16.row.col.f32.bf16.bf16.f32 "
                 "{%0,%1,%2,%3}, {%4,%5,%6,%7}, {%8,%9}, {%0,%1,%2,%3};"
                 : "+f"(d[0]), "+f"(d[1]), "+f"(d[2]), "+f"(d[3])
                 : "r"(a[0]), "r"(a[1]), "r"(a[2]), "r"(a[3]), "r"(b0), "r"(b1));
}

// ---------------------------------------------------------------------------
// Split-bf16 tensor-core GEMM: C[N=4096, M] (+)= A[.,K] @ B[M,K]^T
// A,B as (hi,lo) bf16; D = Ah*Bh + Ah*Bl + Al*Bh, fp32 accum.
// CTA tile 128x128, BK=32, 256 threads (8 warps, 2x4), warp tile 64x32.
// 2-stage cp.async double buffer. SMEM rows padded to 40 bf16 (80 B).
// Requires M%128==0, K%32==0.
// ---------------------------------------------------------------------------
#define BK        32
#define ROWB      80                       // padded row bytes (32 bf16 data + 8 pad)
#define SA_HI     0
#define SA_LO     (128 * ROWB)             // 10240
#define SB_HI     (2 * 128 * ROWB)         // 20480
#define SB_LO     (3 * 128 * ROWB)         // 30720
#define STAGE_B   (4 * 128 * ROWB)         // 40960
#define SMEM_TOTAL (2 * STAGE_B)           // 81920

template <int BETA>
__global__ void __launch_bounds__(256, 1)
tc_gemm(const __nv_bfloat16* __restrict__ Ahi, const __nv_bfloat16* __restrict__ Alo,
        const __nv_bfloat16* __restrict__ Bhi, const __nv_bfloat16* __restrict__ Blo,
        float* __restrict__ C, int M, int K)
{
    extern __shared__ char smem[];
    const uint32_t sb = smem_u32(smem);
    const int t    = threadIdx.x;
    const int lane = t & 31;
    const int w    = t >> 5;
    const int wm   = w >> 2;               // 0..1 -> m offset 64*wm
    const int wn   = w & 3;                // 0..3 -> n offset 32*wn

    // ---- cooperative load mapping: 2 chunks of 16B per matrix per thread ----
    const size_t rs = (size_t)K * 2;       // gmem row stride bytes
    const char* Ah = (const char*)Ahi + (size_t)blockIdx.y * 128 * rs;
    const char* Al = (const char*)Alo + (size_t)blockIdx.y * 128 * rs;
    const char* Bh = (const char*)Bhi + (size_t)blockIdx.x * 128 * rs;
    const char* Bl = (const char*)Blo + (size_t)blockIdx.x * 128 * rs;

    const int KB = K / BK;

    // per-thread (row, chunk) pairs
    int r0 = t >> 2, c0 = t & 3;           // idx j=0
    int r1 = r0 + 64;                      // idx j=1 (t+256)
    uint32_t so0 = (uint32_t)r0 * ROWB + c0 * 16;
    uint32_t so1 = (uint32_t)r1 * ROWB + c0 * 16;
    size_t   go0 = (size_t)r0 * rs + c0 * 16;
    size_t   go1 = (size_t)r1 * rs + c0 * 16;

#define LOAD_STAGE(kb, buf)                                                  \
    do {                                                                     \
        uint32_t st = sb + (buf) * STAGE_B;                                  \
        size_t   kofs = (size_t)(kb) * (BK * 2);                             \
        cpasync16(st + SA_HI + so0, Ah + go0 + kofs);                        \
        cpasync16(st + SA_HI + so1, Ah + go1 + kofs);                        \
        cpasync16(st + SA_LO + so0, Al + go0 + kofs);                        \
        cpasync16(st + SA_LO + so1, Al + go1 + kofs);                        \
        cpasync16(st + SB_HI + so0, Bh + go0 + kofs);                        \
        cpasync16(st + SB_HI + so1, Bh + go1 + kofs);                        \
        cpasync16(st + SB_LO + so0, Bl + go0 + kofs);                        \
        cpasync16(st + SB_LO + so1, Bl + go1 + kofs);                        \
        cp_commit();                                                         \
    } while (0)

    // ---- ldmatrix per-lane address components ----
    // A: lanes 0-15 -> rows m0..15 (@kk), lanes 16-31 -> same rows @k+8 (+16B)
    const uint32_t a_lofs = (uint32_t)(lane & 15) * ROWB + (lane >> 4) * 16;
    // B: lanes {0-7,8-15,16-23,24-31} -> (n0-7,k0-7),(n0-7,k8-15),(n8-15,k0-7),(n8-15,k8-15)
    const uint32_t b_lofs = (uint32_t)((lane & 7) + ((lane >> 4) << 3)) * ROWB +
                            ((lane >> 3) & 1) * 16;

    float acc[4][4][4];
#pragma unroll
    for (int mi = 0; mi < 4; mi++)
#pragma unroll
        for (int ni = 0; ni < 4; ni++)
#pragma unroll
            for (int q = 0; q < 4; q++) acc[mi][ni][q] = 0.f;

    LOAD_STAGE(0, 0);

    for (int kb = 0; kb < KB; kb++) {
        if (kb + 1 < KB) {
            LOAD_STAGE(kb + 1, (kb + 1) & 1);
            cp_wait<1>();
        } else {
            cp_wait<0>();
        }
        __syncthreads();

        const uint32_t st = sb + (kb & 1) * STAGE_B;
#pragma unroll
        for (int kk = 0; kk < 2; kk++) {   // two k16 halves of BK=32
            // FIX (R6): a k16 slice of a bf16 row is 32 BYTES. kk*16 made the
            // kk=1 fragments re-read k8..23 and never read k24..31 ->
            // deterministic O(1) error (rel_err 1.692, volatile-invariant).
            const uint32_t kbyte = kk * 32;
            uint32_t ah[4][4], al[4][4], bhf[2][4], blf[2][4];
#pragma unroll
            for (int mi = 0; mi < 4; mi++) {
                uint32_t base = (uint32_t)(wm * 64 + mi * 16) * ROWB + kbyte + a_lofs;
                ldm4(ah[mi], st + SA_HI + base);
                ldm4(al[mi], st + SA_LO + base);
            }
#pragma unroll
            for (int pr = 0; pr < 2; pr++) {
                uint32_t base = (uint32_t)(wn * 32 + pr * 16) * ROWB + kbyte + b_lofs;
                ldm4(bhf[pr], st + SB_HI + base);
                ldm4(blf[pr], st + SB_LO + base);
            }
#pragma unroll
            for (int mi = 0; mi < 4; mi++)
#pragma unroll
                for (int ni = 0; ni < 4; ni++) {
                    const int pr = ni >> 1, hf = (ni & 1) * 2;
                    mma16816(acc[mi][ni], ah[mi], bhf[pr][hf], bhf[pr][hf + 1]);
                    mma16816(acc[mi][ni], ah[mi], blf[pr][hf], blf[pr][hf + 1]);
                    mma16816(acc[mi][ni], al[mi], bhf[pr][hf], bhf[pr][hf + 1]);
                }
        }
        __syncthreads();
    }

    // ---- epilogue ----
    const int erow = blockIdx.y * 128 + wm * 64 + (lane >> 2);
    const int ecol = blockIdx.x * 128 + wn * 32 + (lane & 3) * 2;
#pragma unroll
    for (int mi = 0; mi < 4; mi++) {
#pragma unroll
        for (int ni = 0; ni < 4; ni++) {
            float* p0 = C + (size_t)(erow + mi * 16) * M + ecol + ni * 8;
            float* p1 = p0 + 8 * M;
            float2 v0 = make_float2(acc[mi][ni][0], acc[mi][ni][1]);
            float2 v1 = make_float2(acc[mi][ni][2], acc[mi][ni][3]);
            if (BETA) {
                float2 o0 = *(float2*)p0, o1 = *(float2*)p1;
                v0.x += o0.x; v0.y += o0.y;
                v1.x += o1.x; v1.y += o1.y;
            }
            *(float2*)p0 = v0;
            *(float2*)p1 = v1;
        }
    }
#undef LOAD_STAGE
}

// ---------------------------------------------------------------------------
// fp32 -> (hi, lo) bf16 split, 4 elems/thread
// ---------------------------------------------------------------------------
__global__ void split4(const float4* __restrict__ src,
                       __nv_bfloat162* __restrict__ hi,
                       __nv_bfloat162* __restrict__ lo, int n4)
{
    int i = blockIdx.x * blockDim.x + threadIdx.x;
    if (i >= n4) return;
    float4 v = src[i];
    __nv_bfloat16 hx = __float2bfloat16(v.x), hy = __float2bfloat16(v.y);
    __nv_bfloat16 hz = __float2bfloat16(v.z), hw = __float2bfloat16(v.w);
    __nv_bfloat16 lx = __float2bfloat16(v.x - __bfloat162float(hx));
    __nv_bfloat16 ly = __float2bfloat16(v.y - __bfloat162float(hy));
    __nv_bfloat16 lz = __float2bfloat16(v.z - __bfloat162float(hz));
    __nv_bfloat16 lw = __float2bfloat16(v.w - __bfloat162float(hw));
    hi[i * 2 + 0] = __nv_bfloat162(hx, hy);
    hi[i * 2 + 1] = __nv_bfloat162(hz, hw);
    lo[i * 2 + 0] = __nv_bfloat162(lx, ly);
    lo[i * 2 + 1] = __nv_bfloat162(lz, lw);
}

// ---------------------------------------------------------------------------
// Taylor coefficients -> split bf16 TMP[t, s*6+g]
// ---------------------------------------------------------------------------
__global__ void taylor_kernel(const float* __restrict__ AU, const float* __restrict__ GP,
                              const float* __restrict__ lp, const float* __restrict__ df,
                              __nv_bfloat16* __restrict__ TMPh, __nv_bfloat16* __restrict__ TMPl)
{
    int idx = blockIdx.x * blockDim.x + threadIdx.x;    // t*1024 + s
    if (idx >= NTOK * SDIM) return;
    int s = idx & (SDIM - 1);

    float au    = AU[idx];
    float delta = GP[idx] - lp[s];
    float neg   = (delta > 0.f) ? 1.f : -1.f;
    float ad    = fabsf(delta);
    float ld    = logf(ad);
    float keep  = (ad <= 2.5f) ? 1.f : 0.f;

    __nv_bfloat162 h[3], l[3];
#pragma unroll
    for (int g = 0; g < 6; g++) {
        int   m = g + 1;
        float dterm = expf(ld * (float)m - df[g]);
        if (m & 1) dterm *= neg;
        float v = dterm * au;
        if (m > 4) v *= keep;
        __nv_bfloat16 hv = __float2bfloat16(v);
        __nv_bfloat16 lv = __float2bfloat16(v - __bfloat162float(hv));
        if (g & 1) { h[g >> 1].y = hv; l[g >> 1].y = lv; }
        else       { h[g >> 1].x = hv; l[g >> 1].x = lv; }
    }
    __nv_bfloat162* ph = (__nv_bfloat162*)(TMPh + (size_t)idx * 6);
    __nv_bfloat162* pl = (__nv_bfloat162*)(TMPl + (size_t)idx * 6);
    ph[0] = h[0]; ph[1] = h[1]; ph[2] = h[2];
    pl[0] = l[0]; pl[1] = l[1]; pl[2] = l[2];
}

// ---------------------------------------------------------------------------
// P = silu(G) * U -> split bf16
// ---------------------------------------------------------------------------
__global__ void silu_split(const float4* __restrict__ G, const float4* __restrict__ U,
                           __nv_bfloat162* __restrict__ Ph, __nv_bfloat162* __restrict__ Pl, int n4)
{
    int i = blockIdx.x * blockDim.x + threadIdx.x;
    if (i >= n4) return;
    float4 g = G[i];
    float4 u = U[i];
    float4 p;
    p.x = g.x / (1.f + expf(-g.x)) * u.x;
    p.y = g.y / (1.f + expf(-g.y)) * u.y;
    p.z = g.z / (1.f + expf(-g.z)) * u.z;
    p.w = g.w / (1.f + expf(-g.w)) * u.w;
    __nv_bfloat16 hx = __float2bfloat16(p.x), hy = __float2bfloat16(p.y);
    __nv_bfloat16 hz = __float2bfloat16(p.z), hw = __float2bfloat16(p.w);
    Ph[i * 2 + 0] = __nv_bfloat162(hx, hy);
    Ph[i * 2 + 1] = __nv_bfloat162(hz, hw);
    Pl[i * 2 + 0] = __nv_bfloat162(__float2bfloat16(p.x - __bfloat162float(hx)),
                                   __float2bfloat16(p.y - __bfloat162float(hy)));
    Pl[i * 2 + 1] = __nv_bfloat162(__float2bfloat16(p.z - __bfloat162float(hz)),
                                   __float2bfloat16(p.w - __bfloat162float(hw)));
}

// ---------------------------------------------------------------------------
// kernel_launch
// ---------------------------------------------------------------------------
static inline void run_split(const float* src, __nv_bfloat16* hi, __nv_bfloat16* lo, size_t n) {
    int n4 = (int)(n >> 2);
    split4<<<(n4 + 255) / 256, 256>>>((const float4*)src, (__nv_bfloat162*)hi, (__nv_bfloat162*)lo, n4);
}

extern "C" void kernel_launch(void* const* d_in, const int* in_sizes, int n_in,
                              void* d_out, int out_size)
{
    const float* X   = (const float*)d_in[0];   // [4096,4096]
    const float* upw = (const float*)d_in[1];   // [1024,4096]
    const float* gw  = (const float*)d_in[2];   // [1024,4096]
    const float* lp  = (const float*)d_in[3];   // [1024]
    const float* lao = (const float*)d_in[4];   // [4096,1024]
    const float* fw  = (const float*)d_in[5];   // [4096,6144]
    const float* df  = (const float*)d_in[6];   // [6]
    const float* fgw = (const float*)d_in[7];   // [9984,4096]
    const float* fuw = (const float*)d_in[8];   // [9984,4096]
    const float* fdw = (const float*)d_in[9];   // [4096,9984]
    float* out       = (float*)d_out;           // [4096,4096]

    cudaFuncSetAttribute(tc_gemm<0>, cudaFuncAttributeMaxDynamicSharedMemorySize, SMEM_TOTAL);
    cudaFuncSetAttribute(tc_gemm<1>, cudaFuncAttributeMaxDynamicSharedMemorySize, SMEM_TOTAL);

#define SYM(p, s) cudaGetSymbolAddress((void**)&p, s)
    __nv_bfloat16 *Xh, *Xl, *upwh, *upwl, *gwh, *gwl, *laoh, *laol, *fwh, *fwl;
    __nv_bfloat16 *fgwh, *fgwl, *fuwh, *fuwl, *fdwh, *fdwl;
    __nv_bfloat16 *AUh, *AUl, *TMPh, *TMPl, *Ph, *Pl;
    float *AU, *GP, *BG, *BU;
    SYM(Xh, g_Xhi);   SYM(Xl, g_Xlo);
    SYM(upwh, g_upwh); SYM(upwl, g_upwl);
    SYM(gwh, g_gwh);   SYM(gwl, g_gwl);
    SYM(laoh, g_laoh); SYM(laol, g_laol);
    SYM(fwh, g_fwh);   SYM(fwl, g_fwl);
    SYM(fgwh, g_fgwh); SYM(fgwl, g_fgwl);
    SYM(fuwh, g_fuwh); SYM(fuwl, g_fuwl);
    SYM(fdwh, g_fdwh); SYM(fdwl, g_fdwl);
    SYM(AU, g_AU);     SYM(GP, g_GP);
    SYM(AUh, g_AUh);   SYM(AUl, g_AUl);
    SYM(TMPh, g_TMPh); SYM(TMPl, g_TMPl);
    SYM(BG, g_BG);     SYM(BU, g_BU);
    SYM(Ph, g_Ph);     SYM(Pl, g_Pl);
#undef SYM

    // --- fp32 -> hi/lo bf16 conversions ---
    run_split(X,   Xh,   Xl,   (size_t)NTOK * HDIM);
    run_split(upw, upwh, upwl, (size_t)SDIM * HDIM);
    run_split(gw,  gwh,  gwl,  (size_t)SDIM * HDIM);
    run_split(lao, laoh, laol, (size_t)HDIM * SDIM);
    run_split(fw,  fwh,  fwl,  (size_t)HDIM * KTAY);
    run_split(fgw, fgwh, fgwl, (size_t)FDIM * HDIM);
    run_split(fuw, fuwh, fuwl, (size_t)FDIM * HDIM);
    run_split(fdw, fdwh, fdwl, (size_t)HDIM * FDIM);

    // 1,2: AU = X @ up_w^T ; GP = X @ gate_w^T          [4096,1024], K=4096
    tc_gemm<0><<<dim3(SDIM / 128, NTOK / 128), 256, SMEM_TOTAL>>>(Xh, Xl, upwh, upwl, AU, SDIM, HDIM);
    tc_gemm<0><<<dim3(SDIM / 128, NTOK / 128), 256, SMEM_TOTAL>>>(Xh, Xl, gwh,  gwl,  GP, SDIM, HDIM);

    // 3: AU -> hi/lo ; Taylor coefficients -> TMP hi/lo
    run_split(AU, AUh, AUl, (size_t)NTOK * SDIM);
    taylor_kernel<<<(NTOK * SDIM) / 256, 256>>>(AU, GP, lp, df, TMPh, TMPl);

    // 4: out = AU @ lao^T                                [4096,4096], K=1024
    tc_gemm<0><<<dim3(HDIM / 128, NTOK / 128), 256, SMEM_TOTAL>>>(AUh, AUl, laoh, laol, out, HDIM, SDIM);

    // 5: out += TMP @ fw^T                               [4096,4096], K=6144
    tc_gemm<1><<<dim3(HDIM / 128, NTOK / 128), 256, SMEM_TOTAL>>>(TMPh, TMPl, fwh, fwl, out, HDIM, KTAY);

    // 6,7: FFN gate / up                                 [4096,9984], K=4096
    tc_gemm<0><<<dim3(FDIM / 128, NTOK / 128), 256, SMEM_TOTAL>>>(Xh, Xl, fgwh, fgwl, BG, FDIM, HDIM);
    tc_gemm<0><<<dim3(FDIM / 128, NTOK / 128), 256, SMEM_TOTAL>>>(Xh, Xl, fuwh, fuwl, BU, FDIM, HDIM);

    // 8: P = silu(G) * U -> hi/lo
    {
        int n4 = (int)(((size_t)NTOK * FDIM) >> 2);
        silu_split<<<(n4 + 255) / 256, 256>>>((const float4*)BG, (const float4*)BU,
                                              (__nv_bfloat162*)Ph, (__nv_bfloat162*)Pl, n4);
    }

    // 9: out += P @ down^T                               [4096,4096], K=9984
    tc_gemm<1><<<dim3(HDIM / 128, NTOK / 128), 256, SMEM_TOTAL>>>(Ph, Pl, fdwh, fdwl, out, HDIM, FDIM);
}

// round 7
// speedup vs baseline: 2.8960x; 1.2404x over previous
#include <cuda_runtime.h>
#include <cuda_bf16.h>
#include <cstdint>

// ---------------------------------------------------------------------------
// Shapes (fixed)
// ---------------------------------------------------------------------------
#define NTOK 4096            // B*T
#define HDIM 4096
#define SDIM 1024
#define FDIM 9984
#define KTAY 6144            // S*G

// ---------------------------------------------------------------------------
// Scratch (__device__ globals; allocation-free)
// ---------------------------------------------------------------------------
__device__ __nv_bfloat16 g_Xhi [NTOK * HDIM], g_Xlo [NTOK * HDIM];
__device__ __nv_bfloat16 g_upwh[SDIM * HDIM], g_upwl[SDIM * HDIM];
__device__ __nv_bfloat16 g_gwh [SDIM * HDIM], g_gwl [SDIM * HDIM];
__device__ __nv_bfloat16 g_laoh[HDIM * SDIM], g_laol[HDIM * SDIM];
__device__ __nv_bfloat16 g_fwh [HDIM * KTAY], g_fwl [HDIM * KTAY];
__device__ __nv_bfloat16 g_fgwh[(size_t)FDIM * HDIM], g_fgwl[(size_t)FDIM * HDIM];
__device__ __nv_bfloat16 g_fuwh[(size_t)FDIM * HDIM], g_fuwl[(size_t)FDIM * HDIM];
__device__ __nv_bfloat16 g_fdwh[(size_t)HDIM * FDIM], g_fdwl[(size_t)HDIM * FDIM];
__device__ float         g_AU  [NTOK * SDIM], g_GP  [NTOK * SDIM];
__device__ __nv_bfloat16 g_AUh [NTOK * SDIM], g_AUl [NTOK * SDIM];
__device__ __nv_bfloat16 g_TMPh[NTOK * KTAY], g_TMPl[NTOK * KTAY];
__device__ float         g_BG  [(size_t)NTOK * FDIM], g_BU[(size_t)NTOK * FDIM];
__device__ __nv_bfloat16 g_Ph  [(size_t)NTOK * FDIM], g_Pl[(size_t)NTOK * FDIM];

// ---------------------------------------------------------------------------
// Baseline-PTX tensor-core helpers (no 'a'-gated instructions)
// ---------------------------------------------------------------------------
__device__ __forceinline__ uint32_t smem_u32(const void* p) {
    uint32_t a;
    asm("{ .reg .u64 t; cvta.to.shared.u64 t, %1; cvt.u32.u64 %0, t; }" : "=r"(a) : "l"(p));
    return a;
}
__device__ __forceinline__ void cpasync16(uint32_t dst, const void* src) {
    asm volatile("cp.async.cg.shared.global [%0], [%1], 16;" :: "r"(dst), "l"(src) : "memory");
}
__device__ __forceinline__ void cp_commit() {
    asm volatile("cp.async.commit_group;" ::: "memory");
}
template <int N>
__device__ __forceinline__ void cp_wait() {
    asm volatile("cp.async.wait_group %0;" :: "n"(N) : "memory");
}
__device__ __forceinline__ void ldm4(uint32_t* r, uint32_t a) {
    asm volatile("ldmatrix.sync.aligned.m8n8.x4.shared.b16 {%0,%1,%2,%3}, [%4];"
                 : "=r"(r[0]), "=r"(r[1]), "=r"(r[2]), "=r"(r[3]) : "r"(a));
}
__device__ __forceinline__ void mma16816(float* d, const uint32_t* a, uint32_t b0, uint32_t b1) {
    asm volatile("mma.sync.aligned.m16n8k16.row.col.f32.bf16.bf16.f32 "
                 "{%0,%1,%2,%3}, {%4,%5,%6,%7}, {%8,%9}, {%0,%1,%2,%3};"
                 : "+f"(d[0]), "+f"(d[1]), "+f"(d[2]), "+f"(d[3])
                 : "r"(a[0]), "r"(a[1]), "r"(a[2]), "r"(a[3]), "r"(b0), "r"(b1));
}

// ---------------------------------------------------------------------------
// Split-bf16 tensor-core GEMM: C[N=4096, M] (+)= A[.,K] @ B[M,K]^T
// A,B as (hi,lo) bf16; D = Ah*Bh + Ah*Bl + Al*Bh, fp32 accum.
// CTA tile 128x128, BK=32, 256 threads (8 warps, 2x4), warp tile 64x32.
// 2-stage cp.async double buffer; 2 CTAs/SM so barrier bubbles of one CTA
// are covered by the other CTA's MMA stream.
// Requires M%128==0, K%32==0.
// ---------------------------------------------------------------------------
#define BK        32
#define ROWB      80                       // padded row bytes (32 bf16 data + 8 pad)
#define SA_HI     0
#define SA_LO     (128 * ROWB)             // 10240
#define SB_HI     (2 * 128 * ROWB)         // 20480
#define SB_LO     (3 * 128 * ROWB)         // 30720
#define STAGE_B   (4 * 128 * ROWB)         // 40960
#define SMEM_TOTAL (2 * STAGE_B)           // 81920 (x2 CTAs = 160KB <= 227KB)

template <int BETA>
__global__ void __launch_bounds__(256, 2)
tc_gemm(const __nv_bfloat16* __restrict__ Ahi, const __nv_bfloat16* __restrict__ Alo,
        const __nv_bfloat16* __restrict__ Bhi, const __nv_bfloat16* __restrict__ Blo,
        float* __restrict__ C, int M, int K)
{
    extern __shared__ char smem[];
    const uint32_t sb = smem_u32(smem);
    const int t    = threadIdx.x;
    const int lane = t & 31;
    const int w    = t >> 5;
    const int wm   = w >> 2;               // 0..1 -> m offset 64*wm
    const int wn   = w & 3;                // 0..3 -> n offset 32*wn

    // ---- cooperative load mapping: 2 chunks of 16B per matrix per thread ----
    const size_t rs = (size_t)K * 2;       // gmem row stride bytes
    const char* Ah = (const char*)Ahi + (size_t)blockIdx.y * 128 * rs;
    const char* Al = (const char*)Alo + (size_t)blockIdx.y * 128 * rs;
    const char* Bh = (const char*)Bhi + (size_t)blockIdx.x * 128 * rs;
    const char* Bl = (const char*)Blo + (size_t)blockIdx.x * 128 * rs;

    const int KB = K / BK;

    // per-thread (row, chunk) pairs
    int r0 = t >> 2, c0 = t & 3;
    int r1 = r0 + 64;
    uint32_t so0 = (uint32_t)r0 * ROWB + c0 * 16;
    uint32_t so1 = (uint32_t)r1 * ROWB + c0 * 16;
    size_t   go0 = (size_t)r0 * rs + c0 * 16;
    size_t   go1 = (size_t)r1 * rs + c0 * 16;

#define LOAD_STAGE(kb, buf)                                                  \
    do {                                                                     \
        uint32_t st = sb + (buf) * STAGE_B;                                  \
        size_t   kofs = (size_t)(kb) * (BK * 2);                             \
        cpasync16(st + SA_HI + so0, Ah + go0 + kofs);                        \
        cpasync16(st + SA_HI + so1, Ah + go1 + kofs);                        \
        cpasync16(st + SA_LO + so0, Al + go0 + kofs);                        \
        cpasync16(st + SA_LO + so1, Al + go1 + kofs);                        \
        cpasync16(st + SB_HI + so0, Bh + go0 + kofs);                        \
        cpasync16(st + SB_HI + so1, Bh + go1 + kofs);                        \
        cpasync16(st + SB_LO + so0, Bl + go0 + kofs);                        \
        cpasync16(st + SB_LO + so1, Bl + go1 + kofs);                        \
        cp_commit();                                                         \
    } while (0)

    // ---- ldmatrix per-lane address components ----
    const uint32_t a_lofs = (uint32_t)(lane & 15) * ROWB + (lane >> 4) * 16;
    const uint32_t b_lofs = (uint32_t)((lane & 7) + ((lane >> 4) << 3)) * ROWB +
                            ((lane >> 3) & 1) * 16;

    float acc[4][4][4];
#pragma unroll
    for (int mi = 0; mi < 4; mi++)
#pragma unroll
        for (int ni = 0; ni < 4; ni++)
#pragma unroll
            for (int q = 0; q < 4; q++) acc[mi][ni][q] = 0.f;

    LOAD_STAGE(0, 0);

    for (int kb = 0; kb < KB; kb++) {
        if (kb + 1 < KB) {
            LOAD_STAGE(kb + 1, (kb + 1) & 1);
            cp_wait<1>();
        } else {
            cp_wait<0>();
        }
        __syncthreads();

        const uint32_t st = sb + (kb & 1) * STAGE_B;
#pragma unroll
        for (int kk = 0; kk < 2; kk++) {   // two k16 halves of BK=32 (32B each)
            const uint32_t kbyte = kk * 32;
            // B fragments for this k16 (16 regs live)
            uint32_t bhf[2][4], blf[2][4];
#pragma unroll
            for (int pr = 0; pr < 2; pr++) {
                uint32_t base = (uint32_t)(wn * 32 + pr * 16) * ROWB + kbyte + b_lofs;
                ldm4(bhf[pr], st + SB_HI + base);
                ldm4(blf[pr], st + SB_LO + base);
            }
            // per row-pair: load A hi/lo (8 regs), issue its 12 MMAs, release
#pragma unroll
            for (int mi = 0; mi < 4; mi++) {
                uint32_t ah[4], al[4];
                uint32_t base = (uint32_t)(wm * 64 + mi * 16) * ROWB + kbyte + a_lofs;
                ldm4(ah, st + SA_HI + base);
                ldm4(al, st + SA_LO + base);
#pragma unroll
                for (int ni = 0; ni < 4; ni++) {
                    const int pr = ni >> 1, hf = (ni & 1) * 2;
                    mma16816(acc[mi][ni], ah, bhf[pr][hf], bhf[pr][hf + 1]);
                    mma16816(acc[mi][ni], ah, blf[pr][hf], blf[pr][hf + 1]);
                    mma16816(acc[mi][ni], al, bhf[pr][hf], bhf[pr][hf + 1]);
                }
            }
        }
        __syncthreads();
    }

    // ---- epilogue ----
    const int erow = blockIdx.y * 128 + wm * 64 + (lane >> 2);
    const int ecol = blockIdx.x * 128 + wn * 32 + (lane & 3) * 2;
#pragma unroll
    for (int mi = 0; mi < 4; mi++) {
#pragma unroll
        for (int ni = 0; ni < 4; ni++) {
            float* p0 = C + (size_t)(erow + mi * 16) * M + ecol + ni * 8;
            float* p1 = p0 + 8 * M;
            float2 v0 = make_float2(acc[mi][ni][0], acc[mi][ni][1]);
            float2 v1 = make_float2(acc[mi][ni][2], acc[mi][ni][3]);
            if (BETA) {
                float2 o0 = *(float2*)p0, o1 = *(float2*)p1;
                v0.x += o0.x; v0.y += o0.y;
                v1.x += o1.x; v1.y += o1.y;
            }
            *(float2*)p0 = v0;
            *(float2*)p1 = v1;
        }
    }
#undef LOAD_STAGE
}

// ---------------------------------------------------------------------------
// fp32 -> (hi, lo) bf16 split, 4 elems/thread
// ---------------------------------------------------------------------------
__global__ void split4(const float4* __restrict__ src,
                       __nv_bfloat162* __restrict__ hi,
                       __nv_bfloat162* __restrict__ lo, int n4)
{
    int i = blockIdx.x * blockDim.x + threadIdx.x;
    if (i >= n4) return;
    float4 v = src[i];
    __nv_bfloat16 hx = __float2bfloat16(v.x), hy = __float2bfloat16(v.y);
    __nv_bfloat16 hz = __float2bfloat16(v.z), hw = __float2bfloat16(v.w);
    __nv_bfloat16 lx = __float2bfloat16(v.x - __bfloat162float(hx));
    __nv_bfloat16 ly = __float2bfloat16(v.y - __bfloat162float(hy));
    __nv_bfloat16 lz = __float2bfloat16(v.z - __bfloat162float(hz));
    __nv_bfloat16 lw = __float2bfloat16(v.w - __bfloat162float(hw));
    hi[i * 2 + 0] = __nv_bfloat162(hx, hy);
    hi[i * 2 + 1] = __nv_bfloat162(hz, hw);
    lo[i * 2 + 0] = __nv_bfloat162(lx, ly);
    lo[i * 2 + 1] = __nv_bfloat162(lz, lw);
}

// ---------------------------------------------------------------------------
// Taylor coefficients -> split bf16 TMP[t, s*6+g]
// ---------------------------------------------------------------------------
__global__ void taylor_kernel(const float* __restrict__ AU, const float* __restrict__ GP,
                              const float* __restrict__ lp, const float* __restrict__ df,
                              __nv_bfloat16* __restrict__ TMPh, __nv_bfloat16* __restrict__ TMPl)
{
    int idx = blockIdx.x * blockDim.x + threadIdx.x;    // t*1024 + s
    if (idx >= NTOK * SDIM) return;
    int s = idx & (SDIM - 1);

    float au    = AU[idx];
    float delta = GP[idx] - lp[s];
    float neg   = (delta > 0.f) ? 1.f : -1.f;
    float ad    = fabsf(delta);
    float ld    = logf(ad);
    float keep  = (ad <= 2.5f) ? 1.f : 0.f;

    __nv_bfloat162 h[3], l[3];
#pragma unroll
    for (int g = 0; g < 6; g++) {
        int   m = g + 1;
        float dterm = expf(ld * (float)m - df[g]);
        if (m & 1) dterm *= neg;
        float v = dterm * au;
        if (m > 4) v *= keep;
        __nv_bfloat16 hv = __float2bfloat16(v);
        __nv_bfloat16 lv = __float2bfloat16(v - __bfloat162float(hv));
        if (g & 1) { h[g >> 1].y = hv; l[g >> 1].y = lv; }
        else       { h[g >> 1].x = hv; l[g >> 1].x = lv; }
    }
    __nv_bfloat162* ph = (__nv_bfloat162*)(TMPh + (size_t)idx * 6);
    __nv_bfloat162* pl = (__nv_bfloat162*)(TMPl + (size_t)idx * 6);
    ph[0] = h[0]; ph[1] = h[1]; ph[2] = h[2];
    pl[0] = l[0]; pl[1] = l[1]; pl[2] = l[2];
}

// ---------------------------------------------------------------------------
// P = silu(G) * U -> split bf16
// ---------------------------------------------------------------------------
__global__ void silu_split(const float4* __restrict__ G, const float4* __restrict__ U,
                           __nv_bfloat162* __restrict__ Ph, __nv_bfloat162* __restrict__ Pl, int n4)
{
    int i = blockIdx.x * blockDim.x + threadIdx.x;
    if (i >= n4) return;
    float4 g = G[i];
    float4 u = U[i];
    float4 p;
    p.x = g.x / (1.f + expf(-g.x)) * u.x;
    p.y = g.y / (1.f + expf(-g.y)) * u.y;
    p.z = g.z / (1.f + expf(-g.z)) * u.z;
    p.w = g.w / (1.f + expf(-g.w)) * u.w;
    __nv_bfloat16 hx = __float2bfloat16(p.x), hy = __float2bfloat16(p.y);
    __nv_bfloat16 hz = __float2bfloat16(p.z), hw = __float2bfloat16(p.w);
    Ph[i * 2 + 0] = __nv_bfloat162(hx, hy);
    Ph[i * 2 + 1] = __nv_bfloat162(hz, hw);
    Pl[i * 2 + 0] = __nv_bfloat162(__float2bfloat16(p.x - __bfloat162float(hx)),
                                   __float2bfloat16(p.y - __bfloat162float(hy)));
    Pl[i * 2 + 1] = __nv_bfloat162(__float2bfloat16(p.z - __bfloat162float(hz)),
                                   __float2bfloat16(p.w - __bfloat162float(hw)));
}

// ---------------------------------------------------------------------------
// kernel_launch
// ---------------------------------------------------------------------------
static inline void run_split(const float* src, __nv_bfloat16* hi, __nv_bfloat16* lo, size_t n) {
    int n4 = (int)(n >> 2);
    split4<<<(n4 + 255) / 256, 256>>>((const float4*)src, (__nv_bfloat162*)hi, (__nv_bfloat162*)lo, n4);
}

extern "C" void kernel_launch(void* const* d_in, const int* in_sizes, int n_in,
                              void* d_out, int out_size)
{
    const float* X   = (const float*)d_in[0];   // [4096,4096]
    const float* upw = (const float*)d_in[1];   // [1024,4096]
    const float* gw  = (const float*)d_in[2];   // [1024,4096]
    const float* lp  = (const float*)d_in[3];   // [1024]
    const float* lao = (const float*)d_in[4];   // [4096,1024]
    const float* fw  = (const float*)d_in[5];   // [4096,6144]
    const float* df  = (const float*)d_in[6];   // [6]
    const float* fgw = (const float*)d_in[7];   // [9984,4096]
    const float* fuw = (const float*)d_in[8];   // [9984,4096]
    const float* fdw = (const float*)d_in[9];   // [4096,9984]
    float* out       = (float*)d_out;           // [4096,4096]

    cudaFuncSetAttribute(tc_gemm<0>, cudaFuncAttributeMaxDynamicSharedMemorySize, SMEM_TOTAL);
    cudaFuncSetAttribute(tc_gemm<1>, cudaFuncAttributeMaxDynamicSharedMemorySize, SMEM_TOTAL);

#define SYM(p, s) cudaGetSymbolAddress((void**)&p, s)
    __nv_bfloat16 *Xh, *Xl, *upwh, *upwl, *gwh, *gwl, *laoh, *laol, *fwh, *fwl;
    __nv_bfloat16 *fgwh, *fgwl, *fuwh, *fuwl, *fdwh, *fdwl;
    __nv_bfloat16 *AUh, *AUl, *TMPh, *TMPl, *Ph, *Pl;
    float *AU, *GP, *BG, *BU;
    SYM(Xh, g_Xhi);   SYM(Xl, g_Xlo);
    SYM(upwh, g_upwh); SYM(upwl, g_upwl);
    SYM(gwh, g_gwh);   SYM(gwl, g_gwl);
    SYM(laoh, g_laoh); SYM(laol, g_laol);
    SYM(fwh, g_fwh);   SYM(fwl, g_fwl);
    SYM(fgwh, g_fgwh); SYM(fgwl, g_fgwl);
    SYM(fuwh, g_fuwh); SYM(fuwl, g_fuwl);
    SYM(fdwh, g_fdwh); SYM(fdwl, g_fdwl);
    SYM(AU, g_AU);     SYM(GP, g_GP);
    SYM(AUh, g_AUh);   SYM(AUl, g_AUl);
    SYM(TMPh, g_TMPh); SYM(TMPl, g_TMPl);
    SYM(BG, g_BG);     SYM(BU, g_BU);
    SYM(Ph, g_Ph);     SYM(Pl, g_Pl);
#undef SYM

    // --- fp32 -> hi/lo bf16 conversions ---
    run_split(X,   Xh,   Xl,   (size_t)NTOK * HDIM);
    run_split(upw, upwh, upwl, (size_t)SDIM * HDIM);
    run_split(gw,  gwh,  gwl,  (size_t)SDIM * HDIM);
    run_split(lao, laoh, laol, (size_t)HDIM * SDIM);
    run_split(fw,  fwh,  fwl,  (size_t)HDIM * KTAY);
    run_split(fgw, fgwh, fgwl, (size_t)FDIM * HDIM);
    run_split(fuw, fuwh, fuwl, (size_t)FDIM * HDIM);
    run_split(fdw, fdwh, fdwl, (size_t)HDIM * FDIM);

    // 1,2: AU = X @ up_w^T ; GP = X @ gate_w^T          [4096,1024], K=4096
    tc_gemm<0><<<dim3(SDIM / 128, NTOK / 128), 256, SMEM_TOTAL>>>(Xh, Xl, upwh, upwl, AU, SDIM, HDIM);
    tc_gemm<0><<<dim3(SDIM / 128, NTOK / 128), 256, SMEM_TOTAL>>>(Xh, Xl, gwh,  gwl,  GP, SDIM, HDIM);

    // 3: AU -> hi/lo ; Taylor coefficients -> TMP hi/lo
    run_split(AU, AUh, AUl, (size_t)NTOK * SDIM);
    taylor_kernel<<<(NTOK * SDIM) / 256, 256>>>(AU, GP, lp, df, TMPh, TMPl);

    // 4: out = AU @ lao^T                                [4096,4096], K=1024
    tc_gemm<0><<<dim3(HDIM / 128, NTOK / 128), 256, SMEM_TOTAL>>>(AUh, AUl, laoh, laol, out, HDIM, SDIM);

    // 5: out += TMP @ fw^T                               [4096,4096], K=6144
    tc_gemm<1><<<dim3(HDIM / 128, NTOK / 128), 256, SMEM_TOTAL>>>(TMPh, TMPl, fwh, fwl, out, HDIM, KTAY);

    // 6,7: FFN gate / up                                 [4096,9984], K=4096
    tc_gemm<0><<<dim3(FDIM / 128, NTOK / 128), 256, SMEM_TOTAL>>>(Xh, Xl, fgwh, fgwl, BG, FDIM, HDIM);
    tc_gemm<0><<<dim3(FDIM / 128, NTOK / 128), 256, SMEM_TOTAL>>>(Xh, Xl, fuwh, fuwl, BU, FDIM, HDIM);

    // 8: P = silu(G) * U -> hi/lo
    {
        int n4 = (int)(((size_t)NTOK * FDIM) >> 2);
        silu_split<<<(n4 + 255) / 256, 256>>>((const float4*)BG, (const float4*)BU,
                                              (__nv_bfloat162*)Ph, (__nv_bfloat162*)Pl, n4);
    }

    // 9: out += P @ down^T                               [4096,4096], K=9984
    tc_gemm<1><<<dim3(HDIM / 128, NTOK / 128), 256, SMEM_TOTAL>>>(Ph, Pl, fdwh, fdwl, out, HDIM, FDIM);
}

// round 9
// speedup vs baseline: 3.2391x; 1.1185x over previous
#include <cuda_runtime.h>
#include <cuda_bf16.h>
#include <cstdint>

// ---------------------------------------------------------------------------
// Shapes (fixed)
// ---------------------------------------------------------------------------
#define NTOK 4096            // B*T
#define HDIM 4096
#define SDIM 1024
#define FDIM 9984
#define KTAY 6144            // S*G

// ---------------------------------------------------------------------------
// Scratch (__device__ globals; allocation-free)
// ---------------------------------------------------------------------------
__device__ __nv_bfloat16 g_Xhi [NTOK * HDIM], g_Xlo [NTOK * HDIM];
__device__ __nv_bfloat16 g_upwh[SDIM * HDIM], g_upwl[SDIM * HDIM];
__device__ __nv_bfloat16 g_gwh [SDIM * HDIM], g_gwl [SDIM * HDIM];
__device__ __nv_bfloat16 g_laoh[HDIM * SDIM], g_laol[HDIM * SDIM];
__device__ __nv_bfloat16 g_fwh [HDIM * KTAY], g_fwl [HDIM * KTAY];
__device__ __nv_bfloat16 g_fgwh[(size_t)FDIM * HDIM], g_fgwl[(size_t)FDIM * HDIM];
__device__ __nv_bfloat16 g_fuwh[(size_t)FDIM * HDIM], g_fuwl[(size_t)FDIM * HDIM];
__device__ __nv_bfloat16 g_fdwh[(size_t)HDIM * FDIM], g_fdwl[(size_t)HDIM * FDIM];
__device__ float         g_AU  [NTOK * SDIM], g_GP  [NTOK * SDIM];
__device__ __nv_bfloat16 g_AUh [NTOK * SDIM], g_AUl [NTOK * SDIM];
__device__ __nv_bfloat16 g_TMPh[NTOK * KTAY], g_TMPl[NTOK * KTAY];
__device__ float         g_BG  [(size_t)NTOK * FDIM], g_BU[(size_t)NTOK * FDIM];
__device__ __nv_bfloat16 g_Ph  [(size_t)NTOK * FDIM], g_Pl[(size_t)NTOK * FDIM];

// ---------------------------------------------------------------------------
// Baseline-PTX tensor-core helpers
// ---------------------------------------------------------------------------
__device__ __forceinline__ uint32_t smem_u32(const void* p) {
    uint32_t a;
    asm("{ .reg .u64 t; cvta.to.shared.u64 t, %1; cvt.u32.u64 %0, t; }" : "=r"(a) : "l"(p));
    return a;
}
__device__ __forceinline__ void cpasync16(uint32_t dst, const void* src) {
    asm volatile("cp.async.cg.shared.global [%0], [%1], 16;" :: "r"(dst), "l"(src) : "memory");
}
__device__ __forceinline__ void cp_commit() {
    asm volatile("cp.async.commit_group;" ::: "memory");
}
template <int N>
__device__ __forceinline__ void cp_wait() {
    asm volatile("cp.async.wait_group %0;" :: "n"(N) : "memory");
}
__device__ __forceinline__ void ldm4(uint32_t* r, uint32_t a) {
    asm volatile("ldmatrix.sync.aligned.m8n8.x4.shared.b16 {%0,%1,%2,%3}, [%4];"
                 : "=r"(r[0]), "=r"(r[1]), "=r"(r[2]), "=r"(r[3]) : "r"(a));
}
__device__ __forceinline__ void mma16816(float* d, const uint32_t* a, uint32_t b0, uint32_t b1) {
    asm volatile("mma.sync.aligned.m16n8k16.row.col.f32.bf16.bf16.f32 "
                 "{%0,%1,%2,%3}, {%4,%5,%6,%7}, {%8,%9}, {%0,%1,%2,%3};"
                 : "+f"(d[0]), "+f"(d[1]), "+f"(d[2]), "+f"(d[3])
                 : "r"(a[0]), "r"(a[1]), "r"(a[2]), "r"(a[3]), "r"(b0), "r"(b1));
}

// ---------------------------------------------------------------------------
// Split-bf16 tensor-core GEMM: C[N=4096, M] (+)= A[.,K] @ B[M,K]^T
// D = Ah*Bh + Ah*Bl + Al*Bh, fp32 accum.
// CTA tile 128x128, BK=32, 256 threads (8 warps, 2x4), warp tile 64x32.
// 3-stage cp.async ring, ONE __syncthreads per k-block, 2 CTAs/SM.
// SMEM: unpadded 64B rows + XOR swizzle (chunk' = chunk ^ ((row>>1)&3)):
//   - every offset is a multiple of 16 (cp.async-legal)
//   - ldmatrix 8-lane groups hit all 32 banks (conflict-free)
// Requires M%128==0, K%32==0.
// ---------------------------------------------------------------------------
#define BK        32
#define ROWB      64                       // 32 bf16, unpadded
#define SA_HI     0
#define SA_LO     (128 * ROWB)             // 8192
#define SB_HI     (2 * 128 * ROWB)         // 16384
#define SB_LO     (3 * 128 * ROWB)         // 24576
#define STAGE_B   (4 * 128 * ROWB)         // 32768
#define NSTAGE    3
#define SMEM_TOTAL (NSTAGE * STAGE_B)      // 98304 (x2 CTAs = 192KB <= 228KB)

template <int BETA>
__global__ void __launch_bounds__(256, 2)
tc_gemm(const __nv_bfloat16* __restrict__ Ahi, const __nv_bfloat16* __restrict__ Alo,
        const __nv_bfloat16* __restrict__ Bhi, const __nv_bfloat16* __restrict__ Blo,
        float* __restrict__ C, int M, int K)
{
    extern __shared__ char smem[];
    const uint32_t sb = smem_u32(smem);
    const int t    = threadIdx.x;
    const int lane = t & 31;
    const int w    = t >> 5;
    const int wm   = w >> 2;               // 0..1 -> m offset 64*wm
    const int wn   = w & 3;                // 0..3 -> n offset 32*wn

    const size_t rs = (size_t)K * 2;       // gmem row stride bytes
    const char* Ah = (const char*)Ahi + (size_t)blockIdx.y * 128 * rs;
    const char* Al = (const char*)Alo + (size_t)blockIdx.y * 128 * rs;
    const char* Bh = (const char*)Bhi + (size_t)blockIdx.x * 128 * rs;
    const char* Bl = (const char*)Blo + (size_t)blockIdx.x * 128 * rs;

    const int KB = K / BK;

    // cooperative store mapping: idx = t (rows 0..63), t+256 (rows 64..127);
    // row = idx>>2, logical chunk = idx&3, physical chunk = c ^ ((row>>1)&3)
    int r0 = t >> 2, c0 = t & 3;
    int r1 = r0 + 64;                      // (r1>>1)&3 == (r0>>1)&3 (+32)
    int cs = c0 ^ ((r0 >> 1) & 3);
    uint32_t so0 = (uint32_t)r0 * ROWB + cs * 16;
    uint32_t so1 = (uint32_t)r1 * ROWB + cs * 16;
    size_t   go0 = (size_t)r0 * rs + c0 * 16;
    size_t   go1 = (size_t)r1 * rs + c0 * 16;

#define LOAD_STAGE(kb, buf)                                                  \
    do {                                                                     \
        uint32_t st = sb + (uint32_t)(buf) * STAGE_B;                        \
        size_t   kofs = (size_t)(kb) * 64;  /* BK=32 bf16 = 64B */           \
        cpasync16(st + SA_HI + so0, Ah + go0 + kofs);                        \
        cpasync16(st + SA_HI + so1, Ah + go1 + kofs);                        \
        cpasync16(st + SA_LO + so0, Al + go0 + kofs);                        \
        cpasync16(st + SA_LO + so1, Al + go1 + kofs);                        \
        cpasync16(st + SB_HI + so0, Bh + go0 + kofs);                        \
        cpasync16(st + SB_HI + so1, Bh + go1 + kofs);                        \
        cpasync16(st + SB_LO + so0, Bl + go0 + kofs);                        \
        cpasync16(st + SB_LO + so1, Bl + go1 + kofs);                        \
        cp_commit();                                                         \
    } while (0)

    // ldmatrix per-lane components.
    // A: lane row = lane&15 (fragment row-bases are multiples of 16, so the
    // swizzle term depends only on lane); logical chunk = kk*2 + (lane>>4).
    const int la_r  = lane & 15;
    const int la_sw = (la_r >> 1) & 3;
    const int la_c  = lane >> 4;           // 0/1
    // B: lane row = (lane&7) + ((lane>>4)<<3); logical chunk = kk*2 + ((lane>>3)&1)
    const int lb_r  = (lane & 7) + ((lane >> 4) << 3);
    const int lb_sw = (lb_r >> 1) & 3;
    const int lb_c  = (lane >> 3) & 1;     // 0/1

    float acc[4][4][4];
#pragma unroll
    for (int mi = 0; mi < 4; mi++)
#pragma unroll
        for (int ni = 0; ni < 4; ni++)
#pragma unroll
            for (int q = 0; q < 4; q++) acc[mi][ni][q] = 0.f;

    LOAD_STAGE(0, 0);
    LOAD_STAGE(1, 1);

    int buf = 0, nbuf = 2;                 // nbuf = (kb+2) % 3
    for (int kb = 0; kb < KB; kb++) {
        if (kb + 1 < KB) cp_wait<1>(); else cp_wait<0>();
        __syncthreads();                   // all warps done computing kb-1
        if (kb + 2 < KB) LOAD_STAGE(kb + 2, nbuf);  // overwrites buf (kb-1)%3

        const uint32_t st = sb + (uint32_t)buf * STAGE_B;
#pragma unroll
        for (int kk = 0; kk < 2; kk++) {   // two k16 halves
            const uint32_t ca = (uint32_t)((kk * 2 + la_c) ^ la_sw) * 16;
            const uint32_t cb = (uint32_t)((kk * 2 + lb_c) ^ lb_sw) * 16;
            uint32_t bhf[2][4], blf[2][4];
#pragma unroll
            for (int pr = 0; pr < 2; pr++) {
                uint32_t base = (uint32_t)(wn * 32 + pr * 16 + lb_r) * ROWB + cb;
                ldm4(bhf[pr], st + SB_HI + base);
                ldm4(blf[pr], st + SB_LO + base);
            }
#pragma unroll
            for (int mi = 0; mi < 4; mi++) {
                uint32_t ah[4], al[4];
                uint32_t base = (uint32_t)(wm * 64 + mi * 16 + la_r) * ROWB + ca;
                ldm4(ah, st + SA_HI + base);
                ldm4(al, st + SA_LO + base);
#pragma unroll
                for (int ni = 0; ni < 4; ni++) {
                    const int pr = ni >> 1, hf = (ni & 1) * 2;
                    mma16816(acc[mi][ni], ah, bhf[pr][hf], bhf[pr][hf + 1]);
                    mma16816(acc[mi][ni], ah, blf[pr][hf], blf[pr][hf + 1]);
                    mma16816(acc[mi][ni], al, bhf[pr][hf], bhf[pr][hf + 1]);
                }
            }
        }
        buf  = (buf  == 2) ? 0 : buf + 1;
        nbuf = (nbuf == 2) ? 0 : nbuf + 1;
    }

    // ---- epilogue ----
    const int erow = blockIdx.y * 128 + wm * 64 + (lane >> 2);
    const int ecol = blockIdx.x * 128 + wn * 32 + (lane & 3) * 2;
#pragma unroll
    for (int mi = 0; mi < 4; mi++) {
#pragma unroll
        for (int ni = 0; ni < 4; ni++) {
            float* p0 = C + (size_t)(erow + mi * 16) * M + ecol + ni * 8;
            float* p1 = p0 + 8 * M;
            float2 v0 = make_float2(acc[mi][ni][0], acc[mi][ni][1]);
            float2 v1 = make_float2(acc[mi][ni][2], acc[mi][ni][3]);
            if (BETA) {
                float2 o0 = *(float2*)p0, o1 = *(float2*)p1;
                v0.x += o0.x; v0.y += o0.y;
                v1.x += o1.x; v1.y += o1.y;
            }
            *(float2*)p0 = v0;
            *(float2*)p1 = v1;
        }
    }
#undef LOAD_STAGE
}

// ---------------------------------------------------------------------------
// fp32 -> (hi, lo) bf16 split. 4 independent float4 per thread (MLP=4).
// ---------------------------------------------------------------------------
__global__ void split4(const float4* __restrict__ src,
                       __nv_bfloat162* __restrict__ hi,
                       __nv_bfloat162* __restrict__ lo, int n4)
{
    int i0 = blockIdx.x * (blockDim.x * 4) + threadIdx.x;
    float4 v[4];
    bool   ok[4];
#pragma unroll
    for (int j = 0; j < 4; j++) {
        int i = i0 + j * 256;
        ok[j] = (i < n4);
        if (ok[j]) v[j] = src[i];
    }
#pragma unroll
    for (int j = 0; j < 4; j++) {
        if (!ok[j]) continue;
        int i = i0 + j * 256;
        __nv_bfloat16 hx = __float2bfloat16(v[j].x), hy = __float2bfloat16(v[j].y);
        __nv_bfloat16 hz = __float2bfloat16(v[j].z), hw = __float2bfloat16(v[j].w);
        hi[i * 2 + 0] = __nv_bfloat162(hx, hy);
        hi[i * 2 + 1] = __nv_bfloat162(hz, hw);
        lo[i * 2 + 0] = __nv_bfloat162(__float2bfloat16(v[j].x - __bfloat162float(hx)),
                                       __float2bfloat16(v[j].y - __bfloat162float(hy)));
        lo[i * 2 + 1] = __nv_bfloat162(__float2bfloat16(v[j].z - __bfloat162float(hz)),
                                       __float2bfloat16(v[j].w - __bfloat162float(hw)));
    }
}

// ---------------------------------------------------------------------------
// Taylor coefficients -> split bf16 TMP[t, s*6+g]
// ---------------------------------------------------------------------------
__global__ void taylor_kernel(const float* __restrict__ AU, const float* __restrict__ GP,
                              const float* __restrict__ lp, const float* __restrict__ df,
                              __nv_bfloat16* __restrict__ TMPh, __nv_bfloat16* __restrict__ TMPl)
{
    int idx = blockIdx.x * blockDim.x + threadIdx.x;    // t*1024 + s
    if (idx >= NTOK * SDIM) return;
    int s = idx & (SDIM - 1);

    float au    = AU[idx];
    float delta = GP[idx] - lp[s];
    float neg   = (delta > 0.f) ? 1.f : -1.f;
    float ad    = fabsf(delta);
    float ld    = logf(ad);
    float keep  = (ad <= 2.5f) ? 1.f : 0.f;

    __nv_bfloat162 h[3], l[3];
#pragma unroll
    for (int g = 0; g < 6; g++) {
        int   m = g + 1;
        float dterm = expf(ld * (float)m - df[g]);
        if (m & 1) dterm *= neg;
        float v = dterm * au;
        if (m > 4) v *= keep;
        __nv_bfloat16 hv = __float2bfloat16(v);
        __nv_bfloat16 lv = __float2bfloat16(v - __bfloat162float(hv));
        if (g & 1) { h[g >> 1].y = hv; l[g >> 1].y = lv; }
        else       { h[g >> 1].x = hv; l[g >> 1].x = lv; }
    }
    __nv_bfloat162* ph = (__nv_bfloat162*)(TMPh + (size_t)idx * 6);
    __nv_bfloat162* pl = (__nv_bfloat162*)(TMPl + (size_t)idx * 6);
    ph[0] = h[0]; ph[1] = h[1]; ph[2] = h[2];
    pl[0] = l[0]; pl[1] = l[1]; pl[2] = l[2];
}

// ---------------------------------------------------------------------------
// P = silu(G) * U -> split bf16. 4 independent float4 pairs per thread.
// ---------------------------------------------------------------------------
__global__ void silu_split(const float4* __restrict__ G, const float4* __restrict__ U,
                           __nv_bfloat162* __restrict__ Ph, __nv_bfloat162* __restrict__ Pl, int n4)
{
    int i0 = blockIdx.x * (blockDim.x * 4) + threadIdx.x;
    float4 g[4], u[4];
    bool   ok[4];
#pragma unroll
    for (int j = 0; j < 4; j++) {
        int i = i0 + j * 256;
        ok[j] = (i < n4);
        if (ok[j]) { g[j] = G[i]; u[j] = U[i]; }
    }
#pragma unroll
    for (int j = 0; j < 4; j++) {
        if (!ok[j]) continue;
        int i = i0 + j * 256;
        float4 p;
        p.x = g[j].x / (1.f + expf(-g[j].x)) * u[j].x;
        p.y = g[j].y / (1.f + expf(-g[j].y)) * u[j].y;
        p.z = g[j].z / (1.f + expf(-g[j].z)) * u[j].z;
        p.w = g[j].w / (1.f + expf(-g[j].w)) * u[j].w;
        __nv_bfloat16 hx = __float2bfloat16(p.x), hy = __float2bfloat16(p.y);
        __nv_bfloat16 hz = __float2bfloat16(p.z), hw = __float2bfloat16(p.w);
        Ph[i * 2 + 0] = __nv_bfloat162(hx, hy);
        Ph[i * 2 + 1] = __nv_bfloat162(hz, hw);
        Pl[i * 2 + 0] = __nv_bfloat162(__float2bfloat16(p.x - __bfloat162float(hx)),
                                       __float2bfloat16(p.y - __bfloat162float(hy)));
        Pl[i * 2 + 1] = __nv_bfloat162(__float2bfloat16(p.z - __bfloat162float(hz)),
                                       __float2bfloat16(p.w - __bfloat162float(hw)));
    }
}

// ---------------------------------------------------------------------------
// kernel_launch
// ---------------------------------------------------------------------------
static inline void run_split(const float* src, __nv_bfloat16* hi, __nv_bfloat16* lo, size_t n) {
    int n4 = (int)(n >> 2);
    split4<<<(n4 + 1023) / 1024, 256>>>((const float4*)src, (__nv_bfloat162*)hi, (__nv_bfloat162*)lo, n4);
}

extern "C" void kernel_launch(void* const* d_in, const int* in_sizes, int n_in,
                              void* d_out, int out_size)
{
    const float* X   = (const float*)d_in[0];   // [4096,4096]
    const float* upw = (const float*)d_in[1];   // [1024,4096]
    const float* gw  = (const float*)d_in[2];   // [1024,4096]
    const float* lp  = (const float*)d_in[3];   // [1024]
    const float* lao = (const float*)d_in[4];   // [4096,1024]
    const float* fw  = (const float*)d_in[5];   // [4096,6144]
    const float* df  = (const float*)d_in[6];   // [6]
    const float* fgw = (const float*)d_in[7];   // [9984,4096]
    const float* fuw = (const float*)d_in[8];   // [9984,4096]
    const float* fdw = (const float*)d_in[9];   // [4096,9984]
    float* out       = (float*)d_out;           // [4096,4096]

    cudaFuncSetAttribute(tc_gemm<0>, cudaFuncAttributeMaxDynamicSharedMemorySize, SMEM_TOTAL);
    cudaFuncSetAttribute(tc_gemm<1>, cudaFuncAttributeMaxDynamicSharedMemorySize, SMEM_TOTAL);

#define SYM(p, s) cudaGetSymbolAddress((void**)&p, s)
    __nv_bfloat16 *Xh, *Xl, *upwh, *upwl, *gwh, *gwl, *laoh, *laol, *fwh, *fwl;
    __nv_bfloat16 *fgwh, *fgwl, *fuwh, *fuwl, *fdwh, *fdwl;
    __nv_bfloat16 *AUh, *AUl, *TMPh, *TMPl, *Ph, *Pl;
    float *AU, *GP, *BG, *BU;
    SYM(Xh, g_Xhi);   SYM(Xl, g_Xlo);
    SYM(upwh, g_upwh); SYM(upwl, g_upwl);
    SYM(gwh, g_gwh);   SYM(gwl, g_gwl);
    SYM(laoh, g_laoh); SYM(laol, g_laol);
    SYM(fwh, g_fwh);   SYM(fwl, g_fwl);
    SYM(fgwh, g_fgwh); SYM(fgwl, g_fgwl);
    SYM(fuwh, g_fuwh); SYM(fuwl, g_fuwl);
    SYM(fdwh, g_fdwh); SYM(fdwl, g_fdwl);
    SYM(AU, g_AU);     SYM(GP, g_GP);
    SYM(AUh, g_AUh);   SYM(AUl, g_AUl);
    SYM(TMPh, g_TMPh); SYM(TMPl, g_TMPl);
    SYM(BG, g_BG);     SYM(BU, g_BU);
    SYM(Ph, g_Ph);     SYM(Pl, g_Pl);
#undef SYM

    // --- fp32 -> hi/lo bf16 conversions ---
    run_split(X,   Xh,   Xl,   (size_t)NTOK * HDIM);
    run_split(upw, upwh, upwl, (size_t)SDIM * HDIM);
    run_split(gw,  gwh,  gwl,  (size_t)SDIM * HDIM);
    run_split(lao, laoh, laol, (size_t)HDIM * SDIM);
    run_split(fw,  fwh,  fwl,  (size_t)HDIM * KTAY);
    run_split(fgw, fgwh, fgwl, (size_t)FDIM * HDIM);
    run_split(fuw, fuwh, fuwl, (size_t)FDIM * HDIM);
    run_split(fdw, fdwh, fdwl, (size_t)HDIM * FDIM);

    // 1,2: AU = X @ up_w^T ; GP = X @ gate_w^T          [4096,1024], K=4096
    tc_gemm<0><<<dim3(SDIM / 128, NTOK / 128), 256, SMEM_TOTAL>>>(Xh, Xl, upwh, upwl, AU, SDIM, HDIM);
    tc_gemm<0><<<dim3(SDIM / 128, NTOK / 128), 256, SMEM_TOTAL>>>(Xh, Xl, gwh,  gwl,  GP, SDIM, HDIM);

    // 3: AU -> hi/lo ; Taylor coefficients -> TMP hi/lo
    run_split(AU, AUh, AUl, (size_t)NTOK * SDIM);
    taylor_kernel<<<(NTOK * SDIM) / 256, 256>>>(AU, GP, lp, df, TMPh, TMPl);

    // 4: out = AU @ lao^T                                [4096,4096], K=1024
    tc_gemm<0><<<dim3(HDIM / 128, NTOK / 128), 256, SMEM_TOTAL>>>(AUh, AUl, laoh, laol, out, HDIM, SDIM);

    // 5: out += TMP @ fw^T                               [4096,4096], K=6144
    tc_gemm<1><<<dim3(HDIM / 128, NTOK / 128), 256, SMEM_TOTAL>>>(TMPh, TMPl, fwh, fwl, out, HDIM, KTAY);

    // 6,7: FFN gate / up                                 [4096,9984], K=4096
    tc_gemm<0><<<dim3(FDIM / 128, NTOK / 128), 256, SMEM_TOTAL>>>(Xh, Xl, fgwh, fgwl, BG, FDIM, HDIM);
    tc_gemm<0><<<dim3(FDIM / 128, NTOK / 128), 256, SMEM_TOTAL>>>(Xh, Xl, fuwh, fuwl, BU, FDIM, HDIM);

    // 8: P = silu(G) * U -> hi/lo
    {
        int n4 = (int)(((size_t)NTOK * FDIM) >> 2);
        silu_split<<<(n4 + 1023) / 1024, 256>>>((const float4*)BG, (const float4*)BU,
                                                (__nv_bfloat162*)Ph, (__nv_bfloat162*)Pl, n4);
    }

    // 9: out += P @ down^T                               [4096,4096], K=9984
    tc_gemm<1><<<dim3(HDIM / 128, NTOK / 128), 256, SMEM_TOTAL>>>(Ph, Pl, fdwh, fdwl, out, HDIM, FDIM);
}